// round 7
// baseline (speedup 1.0000x reference)
#include <cuda_runtime.h>
#include <stdint.h>

#define NMAX 100000
#define EMAX 1600000
#define D 64

// Scratch (static device globals: allocation-free, graph-capturable).
// g_deg starts zero-initialized and is RESET to zero by dinv_kernel each
// launch, so graph replays are deterministic.
__device__ float g_xw[(size_t)NMAX * D];   // holds xs = (x@W) * dinv[row]
__device__ float g_deg[NMAX];
__device__ float g_dinv[NMAX];

// ---------------------------------------------------------------------------
// K1: deg[dst[e]] += 1 for each edge (deg starts at 0; self-loop folded into
// the rsqrt in dinv_kernel).
// ---------------------------------------------------------------------------
__global__ void deg_count_kernel(const int* __restrict__ dst, int E)
{
    int e = blockIdx.x * blockDim.x + threadIdx.x;
    if (e < E) {
        int d = __ldg(&dst[e]);
        atomicAdd(&g_deg[d], 1.0f);
    }
}

// ---------------------------------------------------------------------------
// K2: dinv[i] = rsqrt(deg[i] + 1); deg[i] = 0 (reset for graph replay).
// ---------------------------------------------------------------------------
__global__ void dinv_kernel(int n)
{
    int i = blockIdx.x * blockDim.x + threadIdx.x;
    if (i < n) {
        g_dinv[i] = rsqrtf(g_deg[i] + 1.0f);
        g_deg[i] = 0.0f;
    }
}

// ---------------------------------------------------------------------------
// K3: xs = (x @ W) * dinv[row]; out[row] = xs * dinv[row] + b  (self-loop+bias)
// Block: 256 threads, 64 rows per block. 4 rows x 4 cols register blocking.
// ---------------------------------------------------------------------------
__global__ void __launch_bounds__(256) gemm64_kernel(
    const float* __restrict__ x, const float* __restrict__ W,
    const float* __restrict__ b, float* __restrict__ out, int n)
{
    __shared__ float  sX[64][65];   // padded: kills bank conflicts on column reads
    __shared__ float4 sW[64][16];   // W[k][c4] as float4

    const int t = threadIdx.x;
    const int rowBase = blockIdx.x * 64;

    // Load W (4096 floats = 1024 float4, 4 per thread)
    {
        const float4* W4 = (const float4*)W;
        #pragma unroll
        for (int i = 0; i < 4; i++) {
            int idx = t + i * 256;            // 0..1023
            sW[idx >> 4][idx & 15] = W4[idx];
        }
    }
    // Load 64 rows of x (1024 float4, 4 per thread)
    {
        #pragma unroll
        for (int i = 0; i < 4; i++) {
            int idx = t + i * 256;
            int r = idx >> 4, c4 = idx & 15;
            int row = rowBase + r;
            float4 v = make_float4(0.f, 0.f, 0.f, 0.f);
            if (row < n) v = ((const float4*)(x + (size_t)row * D))[c4];
            sX[r][c4 * 4 + 0] = v.x;
            sX[r][c4 * 4 + 1] = v.y;
            sX[r][c4 * 4 + 2] = v.z;
            sX[r][c4 * 4 + 3] = v.w;
        }
    }
    __syncthreads();

    const int c4 = t & 15;   // which float4 column group
    const int r0 = t >> 4;   // 0..15; rows r0, r0+16, r0+32, r0+48

    float4 acc[4];
    #pragma unroll
    for (int r = 0; r < 4; r++) acc[r] = make_float4(0.f, 0.f, 0.f, 0.f);

    #pragma unroll
    for (int k = 0; k < 64; k++) {
        float4 w = sW[k][c4];
        #pragma unroll
        for (int r = 0; r < 4; r++) {
            float xv = sX[r0 + 16 * r][k];
            acc[r].x += xv * w.x;
            acc[r].y += xv * w.y;
            acc[r].z += xv * w.z;
            acc[r].w += xv * w.w;
        }
    }

    float4 bb = ((const float4*)b)[c4];

    #pragma unroll
    for (int r = 0; r < 4; r++) {
        int row = rowBase + r0 + 16 * r;
        if (row < n) {
            float di = g_dinv[row];
            float4 xs;
            xs.x = acc[r].x * di;
            xs.y = acc[r].y * di;
            xs.z = acc[r].z * di;
            xs.w = acc[r].w * di;
            ((float4*)(g_xw + (size_t)row * D))[c4] = xs;
            float4 o;
            o.x = xs.x * di + bb.x;
            o.y = xs.y * di + bb.y;
            o.z = xs.z * di + bb.z;
            o.w = xs.w * di + bb.w;
            ((float4*)(out + (size_t)row * D))[c4] = o;
        }
    }
}

// ---------------------------------------------------------------------------
// K4: edge scatter: out[dst] += xs[src] * dinv[dst]
// 8 threads per edge, 32B per thread (2x LDG.128 + 2x red.global.add.v4.f32).
// ---------------------------------------------------------------------------
__device__ __forceinline__ void red_add_v4(float* dp, float a, float b, float c, float d)
{
#if !defined(__CUDA_ARCH__) || __CUDA_ARCH__ >= 900
    asm volatile(
        "red.global.add.v4.f32 [%0], {%1, %2, %3, %4};"
        :: "l"(dp), "f"(a), "f"(b), "f"(c), "f"(d)
        : "memory");
#else
    atomicAdd(dp + 0, a);
    atomicAdd(dp + 1, b);
    atomicAdd(dp + 2, c);
    atomicAdd(dp + 3, d);
#endif
}

__global__ void __launch_bounds__(256) scatter_kernel(
    const int* __restrict__ ei, float* __restrict__ out, int E)
{
    unsigned int t = blockIdx.x * 256u + threadIdx.x;
    int e    = (int)(t >> 3);
    int lane = (int)(t & 7);
    if (e >= E) return;

    int s = __ldg(&ei[e]);
    int d = __ldg(&ei[E + e]);
    float c = g_dinv[d];

    const float4* sp = (const float4*)(g_xw + (size_t)s * D) + lane * 2;
    float4 v0 = sp[0];
    float4 v1 = sp[1];

    float* dp = out + (size_t)d * D + lane * 8;
    red_add_v4(dp,     v0.x * c, v0.y * c, v0.z * c, v0.w * c);
    red_add_v4(dp + 4, v1.x * c, v1.y * c, v1.z * c, v1.w * c);
}

// ---------------------------------------------------------------------------
// Launch
// Inputs (metadata order): x [n*64] f32, edge_index [2*E] int32, W [64*64] f32,
//                          b [64] f32. Output: [n*64] f32.
// 4 launches: deg_count, dinv, gemm(+epilogue), scatter.
// ---------------------------------------------------------------------------
extern "C" void kernel_launch(void* const* d_in, const int* in_sizes, int n_in,
                              void* d_out, int out_size)
{
    const float* x  = (const float*)d_in[0];
    const int*   ei = (const int*)d_in[1];
    const float* W  = (const float*)d_in[2];
    const float* b  = (const float*)d_in[3];
    float*       out = (float*)d_out;

    const int n = in_sizes[0] / D;       // 100000
    const int E = in_sizes[1] / 2;       // 1600000

    // K1: degree histogram (dst row)
    deg_count_kernel<<<(E + 255) / 256, 256>>>(ei + E, E);

    // K2: dinv + deg reset
    dinv_kernel<<<(n + 255) / 256, 256>>>(n);

    // K3: projection + dinv scale + self-loop/bias out init
    gemm64_kernel<<<(n + 63) / 64, 256>>>(x, W, b, out, n);

    // K4: edge scatter
    {
        long long total = (long long)E * 8;
        int blocks = (int)((total + 255) / 256);
        scatter_kernel<<<blocks, 256>>>(ei, out, E);
    }
}